// round 16
// baseline (speedup 1.0000x reference)
#include <cuda_runtime.h>
#include <cuda_bf16.h>
#include <cstdint>
#include <cstddef>

#define B_   64
#define S_   256
#define H_   512
#define E_   256
#define V_   32000
#define ML_  32256
#define D2H  1024
#define XW   1536
#define X1W  1280

// warp-level bf16 HMMA, fp32 accumulate (baseline PTX feature on sm_103)
#define MMA_BF16(d, a, b) \
    asm volatile("mma.sync.aligned.m16n8k16.row.col.f32.bf16.bf16.f32 " \
        "{%0,%1,%2,%3}, {%4,%5,%6,%7}, {%8,%9}, {%0,%1,%2,%3};" \
        : "+f"((d)[0]), "+f"((d)[1]), "+f"((d)[2]), "+f"((d)[3]) \
        : "r"((a)[0]), "r"((a)[1]), "r"((a)[2]), "r"((a)[3]), "r"((b)[0]), "r"((b)[1]))

__device__ __forceinline__ void split4(float4 v, uint2& hi, uint2& lo) {
    __nv_bfloat162 h01 = make_bfloat162(__float2bfloat16(v.x), __float2bfloat16(v.y));
    __nv_bfloat162 h23 = make_bfloat162(__float2bfloat16(v.z), __float2bfloat16(v.w));
    __nv_bfloat162 l01 = make_bfloat162(
        __float2bfloat16(v.x - __bfloat162float(h01.x)),
        __float2bfloat16(v.y - __bfloat162float(h01.y)));
    __nv_bfloat162 l23 = make_bfloat162(
        __float2bfloat16(v.z - __bfloat162float(h23.x)),
        __float2bfloat16(v.w - __bfloat162float(h23.y)));
    hi = make_uint2(*(uint32_t*)&h01, *(uint32_t*)&h23);
    lo = make_uint2(*(uint32_t*)&l01, *(uint32_t*)&l23);
}

// ---- scratch ----
__device__ float g_x1[B_ * X1W];
__device__ float g_x [B_ * XW];
__device__ float g_state[B_ * H_];
__device__ float g_logits[B_ * ML_];
__device__ float g_part [8 * B_ * XW];
__device__ float g_part2[8 * B_ * XW];
__device__ float g_scpart[4 * B_ * S_];

#define HS 72
#define HM_BUF  (384 * HS)
#define HM_SMEM (2 * HM_BUF)
#define SC_BUF  (512 * HS)
#define SC_SMEM (2 * SC_BUF + 128 * 5 * 4)

// ---- generic HMMA GEMM body: double-buffer + reg prefetch + term-major MMAs --
__device__ __forceinline__ void hmma64_body(
    const float* __restrict__ A, int lda, const float* __restrict__ Bm,
    const float* __restrict__ bias, float* __restrict__ C, int ldc,
    float* __restrict__ P, int N, int K, int kSplit,
    int bx, int by, uint8_t* __restrict__ smem)
{
    const int tid = threadIdx.x, wid = tid >> 5, lane = tid & 31;
    const int g = lane >> 2, tg = lane & 3;
    const int wm = wid >> 2, wn = wid & 3;
    const int n0 = bx * 128;
    const int kLen = K / kSplit, k0 = by * kLen;
    const int nch = kLen >> 5;

    const int lrow = tid >> 1, lhalf = tid & 1;
    const float* Bsrc = Bm + (size_t)(n0 + lrow) * K + k0 + lhalf * 16;
    const float* Asrc = A + (size_t)lrow * lda + k0 + lhalf * 16;
    const int offA = lrow * HS + lhalf * 32;
    const int offB = lrow * HS + lhalf * 32;

    float acc[2][4][4];
    #pragma unroll
    for (int mi = 0; mi < 2; mi++)
        #pragma unroll
        for (int ni = 0; ni < 4; ni++)
            #pragma unroll
            for (int q = 0; q < 4; q++) acc[mi][ni][q] = 0.f;

    float4 rb[4], ra[4];
    #pragma unroll
    for (int i = 0; i < 4; i++) {
        rb[i] = *(const float4*)(Bsrc + i * 4);
        if (tid < 128) ra[i] = *(const float4*)(Asrc + i * 4);
    }
    {
        uint8_t* buf = smem;
        #pragma unroll
        for (int i = 0; i < 4; i++) {
            uint2 hi, lo;
            split4(rb[i], hi, lo);
            *(uint2*)(buf + 128 * HS + offB + i * 8) = hi;
            *(uint2*)(buf + 256 * HS + offB + i * 8) = lo;
            if (tid < 128) {
                split4(ra[i], hi, lo);
                *(uint2*)(buf + offA + i * 8) = hi;
                *(uint2*)(buf + 64 * HS + offA + i * 8) = lo;
            }
        }
    }
    __syncthreads();

    for (int kc = 0; kc < nch; kc++) {
        const int cur = kc & 1;
        uint8_t* bufc = smem + cur * HM_BUF;
        const bool more = (kc + 1 < nch);
        if (more) {
            #pragma unroll
            for (int i = 0; i < 4; i++) {
                rb[i] = *(const float4*)(Bsrc + (kc + 1) * 32 + i * 4);
                if (tid < 128) ra[i] = *(const float4*)(Asrc + (kc + 1) * 32 + i * 4);
            }
        }
        #pragma unroll
        for (int ks = 0; ks < 2; ks++) {
            const int ko = ks * 32 + tg * 4;
            uint32_t ah[2][4], al[2][4];
            #pragma unroll
            for (int mi = 0; mi < 2; mi++) {
                const uint8_t* p = bufc + (size_t)(wm * 32 + mi * 16 + g) * HS + ko;
                const uint8_t* q = p + 64 * HS;
                ah[mi][0] = *(const uint32_t*)(p);
                ah[mi][1] = *(const uint32_t*)(p + 8 * HS);
                ah[mi][2] = *(const uint32_t*)(p + 16);
                ah[mi][3] = *(const uint32_t*)(p + 8 * HS + 16);
                al[mi][0] = *(const uint32_t*)(q);
                al[mi][1] = *(const uint32_t*)(q + 8 * HS);
                al[mi][2] = *(const uint32_t*)(q + 16);
                al[mi][3] = *(const uint32_t*)(q + 8 * HS + 16);
            }
            uint32_t bh[4][2], bl[4][2];
            #pragma unroll
            for (int ni = 0; ni < 4; ni++) {
                const uint8_t* p = bufc + 128 * HS + (size_t)(wn * 32 + ni * 8 + g) * HS + ko;
                const uint8_t* q = p + 128 * HS;
                bh[ni][0] = *(const uint32_t*)(p);
                bh[ni][1] = *(const uint32_t*)(p + 16);
                bl[ni][0] = *(const uint32_t*)(q);
                bl[ni][1] = *(const uint32_t*)(q + 16);
            }
            // term-major: same-acc MMAs separated by 8 independent ones
            #pragma unroll
            for (int ni = 0; ni < 4; ni++)
                #pragma unroll
                for (int mi = 0; mi < 2; mi++)
                    MMA_BF16(acc[mi][ni], ah[mi], bh[ni]);
            #pragma unroll
            for (int ni = 0; ni < 4; ni++)
                #pragma unroll
                for (int mi = 0; mi < 2; mi++)
                    MMA_BF16(acc[mi][ni], ah[mi], bl[ni]);
            #pragma unroll
            for (int ni = 0; ni < 4; ni++)
                #pragma unroll
                for (int mi = 0; mi < 2; mi++)
                    MMA_BF16(acc[mi][ni], al[mi], bh[ni]);
        }
        if (more) {
            uint8_t* bufn = smem + (cur ^ 1) * HM_BUF;
            #pragma unroll
            for (int i = 0; i < 4; i++) {
                uint2 hi, lo;
                split4(rb[i], hi, lo);
                *(uint2*)(bufn + 128 * HS + offB + i * 8) = hi;
                *(uint2*)(bufn + 256 * HS + offB + i * 8) = lo;
                if (tid < 128) {
                    split4(ra[i], hi, lo);
                    *(uint2*)(bufn + offA + i * 8) = hi;
                    *(uint2*)(bufn + 64 * HS + offA + i * 8) = lo;
                }
            }
        }
        __syncthreads();
    }

    if (kSplit == 1) {
        #pragma unroll
        for (int mi = 0; mi < 2; mi++) {
            int r = wm * 32 + mi * 16 + g;
            #pragma unroll
            for (int ni = 0; ni < 4; ni++) {
                int c = n0 + wn * 32 + ni * 8 + 2 * tg;
                float b0 = bias ? bias[c] : 0.f, b1 = bias ? bias[c+1] : 0.f;
                C[(size_t)r * ldc + c]           = acc[mi][ni][0] + b0;
                C[(size_t)r * ldc + c + 1]       = acc[mi][ni][1] + b1;
                C[(size_t)(r + 8) * ldc + c]     = acc[mi][ni][2] + b0;
                C[(size_t)(r + 8) * ldc + c + 1] = acc[mi][ni][3] + b1;
            }
        }
    } else {
        float* Pz = P + (size_t)by * 64 * N;
        #pragma unroll
        for (int mi = 0; mi < 2; mi++) {
            int r = wm * 32 + mi * 16 + g;
            #pragma unroll
            for (int ni = 0; ni < 4; ni++) {
                int c = n0 + wn * 32 + ni * 8 + 2 * tg;
                Pz[(size_t)r * N + c]           = acc[mi][ni][0];
                Pz[(size_t)r * N + c + 1]       = acc[mi][ni][1];
                Pz[(size_t)(r + 8) * N + c]     = acc[mi][ni][2];
                Pz[(size_t)(r + 8) * N + c + 1] = acc[mi][ni][3];
            }
        }
    }
}

// ---- score_c body (R7 math): double-buffer + reg prefetch + term-major MMAs --
__device__ __forceinline__ void score_c_body(
    const float* __restrict__ enc, const float* __restrict__ W_c,
    const float* __restrict__ b_c, const float* __restrict__ state,
    int sx, int ny, int b, uint8_t* __restrict__ smem)
{
    float (*red)[5] = (float(*)[5])(smem + 2 * SC_BUF);

    const int tid  = threadIdx.x;
    const int wid  = tid >> 5, lane = tid & 31;
    const int g    = lane >> 2, tg = lane & 3;
    const int wm   = wid >> 2,  wn = wid & 3;
    const int s0   = sx * 128, n0 = ny * 128;

    const int lrow = tid >> 1, lhalf = tid & 1;
    const float* Asrc = enc + ((size_t)(b * S_ + s0 + lrow)) * D2H + lhalf * 16;
    const float* Bsrc = W_c + ((size_t)(n0 + lrow)) * D2H + lhalf * 16;
    const int off = lrow * HS + lhalf * 32;

    float acc[4][4][4];
    #pragma unroll
    for (int mi = 0; mi < 4; mi++)
        #pragma unroll
        for (int ni = 0; ni < 4; ni++)
            #pragma unroll
            for (int q = 0; q < 4; q++) acc[mi][ni][q] = 0.f;

    float4 ra[4], rb[4];
    #pragma unroll
    for (int i = 0; i < 4; i++) {
        ra[i] = *(const float4*)(Asrc + i * 4);
        rb[i] = *(const float4*)(Bsrc + i * 4);
    }
    {
        uint8_t* buf = smem;
        #pragma unroll
        for (int i = 0; i < 4; i++) {
            uint2 hi, lo;
            split4(ra[i], hi, lo);
            *(uint2*)(buf + off + i * 8) = hi;
            *(uint2*)(buf + 128 * HS + off + i * 8) = lo;
            split4(rb[i], hi, lo);
            *(uint2*)(buf + 256 * HS + off + i * 8) = hi;
            *(uint2*)(buf + 384 * HS + off + i * 8) = lo;
        }
    }
    __syncthreads();

    for (int kc = 0; kc < 32; kc++) {
        const int cur = kc & 1;
        uint8_t* bufc = smem + cur * SC_BUF;
        const bool more = (kc + 1 < 32);
        if (more) {
            #pragma unroll
            for (int i = 0; i < 4; i++) {
                ra[i] = *(const float4*)(Asrc + (kc + 1) * 32 + i * 4);
                rb[i] = *(const float4*)(Bsrc + (kc + 1) * 32 + i * 4);
            }
        }
        #pragma unroll
        for (int ks = 0; ks < 2; ks++) {
            const int ko = ks * 32 + tg * 4;
            uint32_t ah[4][4], al[4][4];
            #pragma unroll
            for (int mi = 0; mi < 4; mi++) {
                const uint8_t* p = bufc + (size_t)(wm * 64 + mi * 16 + g) * HS + ko;
                const uint8_t* q = p + 128 * HS;
                ah[mi][0] = *(const uint32_t*)(p);
                ah[mi][1] = *(const uint32_t*)(p + 8 * HS);
                ah[mi][2] = *(const uint32_t*)(p + 16);
                ah[mi][3] = *(const uint32_t*)(p + 8 * HS + 16);
                al[mi][0] = *(const uint32_t*)(q);
                al[mi][1] = *(const uint32_t*)(q + 8 * HS);
                al[mi][2] = *(const uint32_t*)(q + 16);
                al[mi][3] = *(const uint32_t*)(q + 8 * HS + 16);
            }
            uint32_t bh[4][2], bl[4][2];
            #pragma unroll
            for (int ni = 0; ni < 4; ni++) {
                const uint8_t* p = bufc + 256 * HS + (size_t)(wn * 32 + ni * 8 + g) * HS + ko;
                const uint8_t* q = p + 128 * HS;
                bh[ni][0] = *(const uint32_t*)(p);
                bh[ni][1] = *(const uint32_t*)(p + 16);
                bl[ni][0] = *(const uint32_t*)(q);
                bl[ni][1] = *(const uint32_t*)(q + 16);
            }
            // term-major: same-acc MMAs separated by 16 independent ones
            #pragma unroll
            for (int ni = 0; ni < 4; ni++)
                #pragma unroll
                for (int mi = 0; mi < 4; mi++)
                    MMA_BF16(acc[mi][ni], ah[mi], bh[ni]);
            #pragma unroll
            for (int ni = 0; ni < 4; ni++)
                #pragma unroll
                for (int mi = 0; mi < 4; mi++)
                    MMA_BF16(acc[mi][ni], ah[mi], bl[ni]);
            #pragma unroll
            for (int ni = 0; ni < 4; ni++)
                #pragma unroll
                for (int mi = 0; mi < 4; mi++)
                    MMA_BF16(acc[mi][ni], al[mi], bh[ni]);
        }
        if (more) {
            uint8_t* bufn = smem + (cur ^ 1) * SC_BUF;
            #pragma unroll
            for (int i = 0; i < 4; i++) {
                uint2 hi, lo;
                split4(ra[i], hi, lo);
                *(uint2*)(bufn + off + i * 8) = hi;
                *(uint2*)(bufn + 128 * HS + off + i * 8) = lo;
                split4(rb[i], hi, lo);
                *(uint2*)(bufn + 256 * HS + off + i * 8) = hi;
                *(uint2*)(bufn + 384 * HS + off + i * 8) = lo;
            }
        }
        __syncthreads();
    }

    float pr[4][2];
    #pragma unroll
    for (int mi = 0; mi < 4; mi++) { pr[mi][0] = 0.f; pr[mi][1] = 0.f; }
    #pragma unroll
    for (int ni = 0; ni < 4; ni++) {
        int c0 = n0 + wn * 32 + ni * 8 + 2 * tg;
        float bc0 = b_c[c0], bc1 = b_c[c0 + 1];
        float st0 = state[(size_t)b * H_ + c0], st1 = state[(size_t)b * H_ + c0 + 1];
        #pragma unroll
        for (int mi = 0; mi < 4; mi++) {
            pr[mi][0] += tanhf(acc[mi][ni][0] + bc0) * st0 + tanhf(acc[mi][ni][1] + bc1) * st1;
            pr[mi][1] += tanhf(acc[mi][ni][2] + bc0) * st0 + tanhf(acc[mi][ni][3] + bc1) * st1;
        }
    }
    #pragma unroll
    for (int mi = 0; mi < 4; mi++) {
        #pragma unroll
        for (int h = 0; h < 2; h++) {
            float v = pr[mi][h];
            v += __shfl_xor_sync(0xffffffffu, v, 1);
            v += __shfl_xor_sync(0xffffffffu, v, 2);
            if (tg == 0) red[wm * 64 + mi * 16 + h * 8 + g][wn] = v;
        }
    }
    __syncthreads();
    if (tid < 128) {
        float s = red[tid][0] + red[tid][1] + red[tid][2] + red[tid][3];
        g_scpart[(size_t)ny * (B_ * S_) + b * S_ + s0 + tid] = s;
    }
}

// ---- merged scores: score_c first (long blocks), score_g last ---------------
#define SG_BLOCKS (V_ / 128)
__global__ void __launch_bounds__(256) scores_kernel(
    const float* __restrict__ W_o, const float* __restrict__ b_o,
    const float* __restrict__ enc, const float* __restrict__ W_c,
    const float* __restrict__ b_c)
{
    extern __shared__ __align__(16) uint8_t smem[];
    if (blockIdx.x < 512) {
        int idx = blockIdx.x;
        score_c_body(enc, W_c, b_c, g_state, idx & 1, (idx >> 1) & 3, idx >> 3, smem);
    } else {
        hmma64_body(g_state, H_, W_o, b_o, g_logits, ML_, nullptr,
                    V_, H_, 1, blockIdx.x - 512, 0, smem);
    }
}

// ---- fused attention ----
__global__ void __launch_bounds__(1024) attn_fused(
    const float* __restrict__ enc, const int* __restrict__ seq,
    const int* __restrict__ input_idx, const float* __restrict__ ppc,
    const float* __restrict__ table, const float* __restrict__ b_aw,
    const float* __restrict__ pre_state, const float* __restrict__ W_aw)
{
    __shared__ float ps[H_];
    __shared__ float sm[D2H];
    __shared__ float w[S_], sw[S_];
    __shared__ float red[S_];
    const int b = blockIdx.x, t = threadIdx.x;
    const int warp = t >> 5, lane = t & 31;

    if (t < E_) {
        int idx = input_idx[b];
        if (idx >= V_) idx = 2;
        g_x1[b * X1W + D2H + t] = table[(size_t)idx * E_ + t];
    }
    if (t < H_) ps[t] = pre_state[b * H_ + t];
    if (t < S_) {
        int idxb = input_idx[b];
        sw[t] = (seq[b * S_ + t] == idxb) ? ppc[b * S_ + t] : 0.f;
    }
    __syncthreads();

    #pragma unroll
    for (int r = 0; r < 32; r++) {
        int d = r * 32 + warp;
        const float4* wrow = (const float4*)(W_aw + (size_t)d * H_);
        float sum = 0.f;
        #pragma unroll
        for (int qi = 0; qi < 4; qi++) {
            int q = lane + qi * 32;
            float4 v = wrow[q];
            sum += v.x*ps[q*4] + v.y*ps[q*4+1] + v.z*ps[q*4+2] + v.w*ps[q*4+3];
        }
        #pragma unroll
        for (int o = 16; o; o >>= 1) sum += __shfl_down_sync(0xffffffffu, sum, o);
        if (lane == 0) sm[d] = sum + b_aw[d];
    }
    __syncthreads();

    #pragma unroll
    for (int r = 0; r < 8; r++) {
        int s = warp * 8 + r;
        const float4* row = (const float4*)(enc + ((size_t)b * S_ + s) * D2H);
        float sum = 0.f;
        #pragma unroll
        for (int qi = 0; qi < 8; qi++) {
            int q = lane + qi * 32;
            float4 v = row[q];
            sum += v.x*sm[q*4] + v.y*sm[q*4+1] + v.z*sm[q*4+2] + v.w*sm[q*4+3];
        }
        #pragma unroll
        for (int o = 16; o; o >>= 1) sum += __shfl_down_sync(0xffffffffu, sum, o);
        if (lane == 0) w[s] = sum;
    }
    __syncthreads();

    if (t < S_) red[t] = w[t];
    __syncthreads();
    for (int o = 128; o; o >>= 1) { if (t < o) red[t] = fmaxf(red[t], red[t+o]); __syncthreads(); }
    float mx = red[0];
    __syncthreads();
    if (t < S_) { w[t] = expf(w[t] - mx); red[t] = w[t]; }
    __syncthreads();
    for (int o = 128; o; o >>= 1) { if (t < o) red[t] += red[t+o]; __syncthreads(); }
    float inv = 1.f / red[0];
    __syncthreads();
    if (t < S_) w[t] *= inv;
    __syncthreads();

    const float* e = enc + (size_t)b * S_ * D2H + t;
    float ctx = 0.f, sel = 0.f;
    #pragma unroll 8
    for (int s = 0; s < S_; s++) {
        float v = e[(size_t)s * D2H];
        ctx = fmaf(w[s], v, ctx);
        sel = fmaf(sw[s], v, sel);
    }
    g_x1[b * X1W + t]     = ctx;
    g_x [b * XW + H_ + t] = sel;
}

// ---- L2: W_ac gemm (32 blocks) + gh gemm (96 blocks) ----
__global__ void __launch_bounds__(256) wac_gh_kernel(
    const float* __restrict__ x1, const float* __restrict__ W_ac,
    const float* __restrict__ pre_state, const float* __restrict__ W_hh)
{
    extern __shared__ __align__(16) uint8_t smem[];
    int i = blockIdx.x;
    if (i < 32)
        hmma64_body(x1, X1W, W_ac, nullptr, nullptr, 0, g_part, H_, X1W, 8,
                    i & 3, i >> 2, smem);
    else {
        int j = i - 32;
        hmma64_body(pre_state, H_, W_hh, nullptr, nullptr, 0, g_part2, XW, H_, 8,
                    j % 12, j / 12, smem);
    }
}

__global__ void splitk_reduce(const float* __restrict__ bias,
                              float* __restrict__ C, int ldc,
                              const float* __restrict__ P, int N, int kSplit)
{
    int idx = blockIdx.x * blockDim.x + threadIdx.x;
    int total = 64 * N;
    if (idx >= total) return;
    int m = idx / N, n = idx - m * N;
    float s = bias ? bias[n] : 0.f;
    for (int z = 0; z < kSplit; z++) s += P[(size_t)z * total + idx];
    C[(size_t)m * ldc + n] = s;
}

// ---- gi gemm ----
__global__ void __launch_bounds__(256) gi_kernel(const float* __restrict__ W_ih)
{
    extern __shared__ __align__(16) uint8_t smem[];
    hmma64_body(g_x, XW, W_ih, nullptr, nullptr, 0, g_part, XW, XW, 8,
                blockIdx.x, blockIdx.y, smem);
}

// ---- fused GRU ----
__global__ void __launch_bounds__(512) gru_fused(
    const float* __restrict__ pre_state,
    const float* __restrict__ b_ih, const float* __restrict__ b_hh,
    float* __restrict__ out_state)
{
    const int b = blockIdx.x, h = threadIdx.x;
    float ir = b_ih[h], iz = b_ih[H_ + h], in_ = b_ih[2*H_ + h];
    float hr = b_hh[h], hz = b_hh[H_ + h], hn  = b_hh[2*H_ + h];
    #pragma unroll
    for (int z = 0; z < 8; z++) {
        size_t base = (size_t)z * 64 * XW + (size_t)b * XW;
        ir  += g_part [base + h];
        iz  += g_part [base + H_ + h];
        in_ += g_part [base + 2*H_ + h];
        hr  += g_part2[base + h];
        hz  += g_part2[base + H_ + h];
        hn  += g_part2[base + 2*H_ + h];
    }
    float r = 1.f / (1.f + expf(-(ir + hr)));
    float z = 1.f / (1.f + expf(-(iz + hz)));
    float n = tanhf(in_ + r * hn);
    float ps = pre_state[b * H_ + h];
    float st = (1.f - z) * n + z * ps;
    g_state[b * H_ + h] = st;
    out_state[b * H_ + h] = st;
}

// ---- fused: scred + big softmax + prob_g write + prob_c scatter ----
__global__ void __launch_bounds__(1024) softmax_probc(
    const int* __restrict__ seq, float* __restrict__ out)
{
    const int b = blockIdx.x, t = threadIdx.x;
    float* row = g_logits + (size_t)b * ML_;
    float* orow = out + (size_t)b * ML_;
    __shared__ float sred[32];
    __shared__ float pc[S_];
    __shared__ int   sq[S_];

    if (t < S_) {
        int idx = b * S_ + t;
        row[V_ + t] = g_scpart[idx] + g_scpart[B_*S_ + idx]
                    + g_scpart[2*B_*S_ + idx] + g_scpart[3*B_*S_ + idx];
        sq[t] = seq[b * S_ + t];
    }
    __syncthreads();

    float m = -1e30f;
    for (int i = t; i < ML_; i += 1024) m = fmaxf(m, row[i]);
    #pragma unroll
    for (int o = 16; o; o >>= 1) m = fmaxf(m, __shfl_xor_sync(0xffffffffu, m, o));
    if ((t & 31) == 0) sred[t >> 5] = m;
    __syncthreads();
    if (t < 32) {
        float x = sred[t];
        #pragma unroll
        for (int o = 16; o; o >>= 1) x = fmaxf(x, __shfl_xor_sync(0xffffffffu, x, o));
        sred[t] = x;
    }
    __syncthreads();
    m = sred[0];
    __syncthreads();
    float sum = 0.f;
    for (int i = t; i < ML_; i += 1024) {
        float e = expf(row[i] - m);
        row[i] = e;
        sum += e;
    }
    #pragma unroll
    for (int o = 16; o; o >>= 1) sum += __shfl_xor_sync(0xffffffffu, sum, o);
    if ((t & 31) == 0) sred[t >> 5] = sum;
    __syncthreads();
    if (t < 32) {
        float x = sred[t];
        #pragma unroll
        for (int o = 16; o; o >>= 1) x += __shfl_xor_sync(0xffffffffu, x, o);
        sred[t] = x;
    }
    __syncthreads();
    float inv = 1.f / sred[0];
    for (int i = t; i < ML_; i += 1024) {
        float v = row[i] * inv;
        if (i < V_) orow[i] = v;
        else { orow[i] = 0.f; pc[i - V_] = v; }
    }
    __syncthreads();

    if (t < S_) {
        int tok = sq[t];
        float s = 0.f;
        bool first = true;
        for (int i = 0; i < S_; i++) {
            bool mq = (sq[i] == tok);
            if (mq) s += pc[i];
            if (mq && i < t) first = false;
        }
        out[(size_t)B_ * ML_ + (size_t)B_ * H_ + b * S_ + t] = s;
        if (first) orow[tok] += s;
    }
}

// ---- launch ----
extern "C" void kernel_launch(void* const* d_in, const int* in_sizes, int n_in,
                              void* d_out, int out_size)
{
    const int*   input_idx = (const int*)  d_in[0];
    const float* enc       = (const float*)d_in[1];
    const int*   seq       = (const int*)  d_in[2];
    const float* pre_state = (const float*)d_in[3];
    const float* ppc       = (const float*)d_in[4];
    const float* table     = (const float*)d_in[5];
    const float* W_aw = (const float*)d_in[6];  const float* b_aw = (const float*)d_in[7];
    const float* W_ac = (const float*)d_in[8];  const float* b_ac = (const float*)d_in[9];
    const float* W_ih = (const float*)d_in[10]; const float* b_ih = (const float*)d_in[11];
    const float* W_hh = (const float*)d_in[12]; const float* b_hh = (const float*)d_in[13];
    const float* W_o  = (const float*)d_in[14]; const float* b_o  = (const float*)d_in[15];
    const float* W_c  = (const float*)d_in[16]; const float* b_c  = (const float*)d_in[17];
    float* out = (float*)d_out;

    float *x1, *x, *part;
    cudaGetSymbolAddress((void**)&x1,   g_x1);
    cudaGetSymbolAddress((void**)&x,    g_x);
    cudaGetSymbolAddress((void**)&part, g_part);

    cudaFuncSetAttribute(scores_kernel, cudaFuncAttributeMaxDynamicSharedMemorySize, SC_SMEM);
    cudaFuncSetAttribute(wac_gh_kernel, cudaFuncAttributeMaxDynamicSharedMemorySize, HM_SMEM);
    cudaFuncSetAttribute(gi_kernel,     cudaFuncAttributeMaxDynamicSharedMemorySize, HM_SMEM);

    // L1: fused attention
    attn_fused<<<B_, 1024>>>(enc, seq, input_idx, ppc, table, b_aw, pre_state, W_aw);

    // L2: W_ac gemm + gh gemm packed
    wac_gh_kernel<<<32 + 96, 256, HM_SMEM>>>(x1, W_ac, pre_state, W_hh);

    // L3: reduce W_ac partials -> g_x[:,0:512]
    splitk_reduce<<<(B_ * H_ + 255) / 256, 256>>>(b_ac, x, XW, part, H_, 8);

    // L4: gi gemm
    gi_kernel<<<dim3(XW / 128, 8), 256, HM_SMEM>>>(W_ih);

    // L5: GRU -> g_state + state output
    gru_fused<<<B_, H_>>>(pre_state, b_ih, b_hh, out + (size_t)B_ * ML_);

    // L6: merged score_c (long, first) + score_g (short, last)
    scores_kernel<<<512 + SG_BLOCKS, 256, SC_SMEM>>>(W_o, b_o, enc, W_c, b_c);

    // L7: softmax + outputs
    softmax_probc<<<B_, 1024>>>(seq, out);
}